// round 1
// baseline (speedup 1.0000x reference)
#include <cuda_runtime.h>

#define D        192          // input cube edge
#define OUTD     186          // valid-conv output edge (192-6)
#define TILE     16           // output tile edge in y,x
#define IN_T     22           // TILE + 6 input patch edge
#define ZC       4            // z chunks
#define ZCS      47           // ceil(186/4)
#define NTHREADS 256

__device__ double g_ssim_acc;

__global__ void ssim_zero_kernel() {
    g_ssim_acc = 0.0;
}

__global__ __launch_bounds__(NTHREADS)
void ssim_main_kernel(const float* __restrict__ x, const float* __restrict__ y) {
    __shared__ float sx[IN_T][IN_T];
    __shared__ float sy[IN_T][IN_T];
    __shared__ float txb[5][IN_T][TILE];   // x-conved fields
    __shared__ float red[NTHREADS];

    const int t   = threadIdx.x;
    const int txi = t & (TILE - 1);
    const int tyi = t >> 4;

    const int tileX = blockIdx.x;
    const int tileY = blockIdx.y;
    const int bz    = blockIdx.z;
    const int batch = bz / ZC;
    const int chunk = bz % ZC;

    const int z0 = chunk * ZCS;
    const int z1 = min(z0 + ZCS, OUTD);    // output z range [z0, z1)

    const size_t plane = (size_t)D * D;
    const float* xb = x + (size_t)batch * plane * D;
    const float* yb = y + (size_t)batch * plane * D;

    // separable Gaussian weights: w[i] = exp(-c^2/(2*sigma^2)) / sum
    float w[7];
    {
        float s = 0.0f;
        #pragma unroll
        for (int i = 0; i < 7; i++) {
            float c = (float)i - 3.0f;
            w[i] = expf(-(c * c) / 4.5f);   // 2*1.5^2 = 4.5
            s += w[i];
        }
        float inv = 1.0f / s;
        #pragma unroll
        for (int i = 0; i < 7; i++) w[i] *= inv;
    }

    const int gx0 = tileX * TILE;
    const int gy0 = tileY * TILE;

    // per-thread z ring: 5 fields x 7 slices
    float r0[7], r1[7], r2[7], r3[7], r4[7];
    #pragma unroll
    for (int j = 0; j < 7; j++) { r0[j]=0.f; r1[j]=0.f; r2[j]=0.f; r3[j]=0.f; r4[j]=0.f; }

    const bool out_valid_xy = (gy0 + tyi < OUTD) && (gx0 + txi < OUTD);

    const float c1 = 1e-4f;   // (0.01*1)^2
    const float c2 = 9e-4f;   // (0.03*1)^2

    float acc = 0.0f;

    for (int zi = z0; zi < z1 + 6; ++zi) {
        // ---- load raw slice zi (22x22 patch of x and y) ----
        const float* xs = xb + (size_t)zi * plane;
        const float* ys = yb + (size_t)zi * plane;
        #pragma unroll
        for (int p = t; p < IN_T * IN_T; p += NTHREADS) {
            int yy = p / IN_T;
            int xx = p - yy * IN_T;
            int gy = gy0 + yy;
            int gx = gx0 + xx;
            float a = 0.0f, b = 0.0f;
            if (gy < D && gx < D) {
                size_t off = (size_t)gy * D + gx;
                a = __ldg(xs + off);
                b = __ldg(ys + off);
            }
            sx[yy][xx] = a;
            sy[yy][xx] = b;
        }
        __syncthreads();

        // ---- x-direction conv of 5 fields: (22 rows x 16 out cols) ----
        #pragma unroll
        for (int p = t; p < IN_T * TILE; p += NTHREADS) {
            int yy = p >> 4;
            int xo = p & (TILE - 1);
            float s0 = 0.f, s1 = 0.f, s2 = 0.f, s3 = 0.f, s4 = 0.f;
            #pragma unroll
            for (int k = 0; k < 7; k++) {
                float a  = sx[yy][xo + k];
                float b  = sy[yy][xo + k];
                float wk = w[k];
                s0 += wk * a;
                s1 += wk * b;
                s2 += wk * (a * a);
                s3 += wk * (b * b);
                s4 += wk * (a * b);
            }
            txb[0][yy][xo] = s0;
            txb[1][yy][xo] = s1;
            txb[2][yy][xo] = s2;
            txb[3][yy][xo] = s3;
            txb[4][yy][xo] = s4;
        }
        __syncthreads();

        // ---- y-direction conv for this thread's (tyi, txi) ----
        float v0 = 0.f, v1 = 0.f, v2 = 0.f, v3 = 0.f, v4 = 0.f;
        #pragma unroll
        for (int k = 0; k < 7; k++) {
            float wk = w[k];
            v0 += wk * txb[0][tyi + k][txi];
            v1 += wk * txb[1][tyi + k][txi];
            v2 += wk * txb[2][tyi + k][txi];
            v3 += wk * txb[3][tyi + k][txi];
            v4 += wk * txb[4][tyi + k][txi];
        }

        // ---- shift z ring ----
        #pragma unroll
        for (int j = 0; j < 6; j++) {
            r0[j] = r0[j + 1]; r1[j] = r1[j + 1]; r2[j] = r2[j + 1];
            r3[j] = r3[j + 1]; r4[j] = r4[j + 1];
        }
        r0[6] = v0; r1[6] = v1; r2[6] = v2; r3[6] = v3; r4[6] = v4;

        // ---- z-direction conv + SSIM once ring is full ----
        if (zi - z0 >= 6 && out_valid_xy) {
            float mu1 = 0.f, mu2 = 0.f, ex2 = 0.f, ey2 = 0.f, exy = 0.f;
            #pragma unroll
            for (int k = 0; k < 7; k++) {
                float wk = w[k];
                mu1 += wk * r0[k];
                mu2 += wk * r1[k];
                ex2 += wk * r2[k];
                ey2 += wk * r3[k];
                exy += wk * r4[k];
            }
            float mu1sq  = mu1 * mu1;
            float mu2sq  = mu2 * mu2;
            float mu1mu2 = mu1 * mu2;
            float sig1   = ex2 - mu1sq;
            float sig2   = ey2 - mu2sq;
            float sig12  = exy - mu1mu2;
            float vA = 2.0f * sig12 + c2;
            float vB = sig1 + sig2 + c2;
            float num = (2.0f * mu1mu2 + c1) * vA;
            float den = (mu1sq + mu2sq + c1) * vB;
            acc += num / den;
        }
    }

    // ---- block reduction ----
    red[t] = acc;
    __syncthreads();
    #pragma unroll
    for (int s = NTHREADS / 2; s > 0; s >>= 1) {
        if (t < s) red[t] += red[t + s];
        __syncthreads();
    }
    if (t == 0) {
        atomicAdd(&g_ssim_acc, (double)red[0]);
    }
}

__global__ void ssim_finalize_kernel(float* __restrict__ out) {
    // N = 2 * 186^3 = 12,869,712
    out[0] = (float)(g_ssim_acc / 12869712.0);
}

extern "C" void kernel_launch(void* const* d_in, const int* in_sizes, int n_in,
                              void* d_out, int out_size) {
    const float* x = (const float*)d_in[0];
    const float* y = (const float*)d_in[1];
    float* out = (float*)d_out;

    ssim_zero_kernel<<<1, 1>>>();

    dim3 grid(12, 12, 2 * ZC);   // 12x16=192 covers 186 in y,x; z: batch*chunk
    ssim_main_kernel<<<grid, NTHREADS>>>(x, y);

    ssim_finalize_kernel<<<1, 1>>>(out);
}

// round 2
// speedup vs baseline: 1.1932x; 1.1932x over previous
#include <cuda_runtime.h>

#define D    192
#define OUTD 186
#define TX   16
#define TY   32
#define INX  22
#define INY  38
#define ZCS  47
#define NT   256

typedef unsigned long long u64;

__device__ __forceinline__ u64 pack2(float lo, float hi){
    u64 r; asm("mov.b64 %0,{%1,%2};":"=l"(r):"f"(lo),"f"(hi)); return r;
}
__device__ __forceinline__ void unpack2(u64 v, float& lo, float& hi){
    asm("mov.b64 {%0,%1},%2;":"=f"(lo),"=f"(hi):"l"(v));
}
__device__ __forceinline__ u64 fma2(u64 a, u64 b, u64 c){
    u64 d; asm("fma.rn.f32x2 %0,%1,%2,%3;":"=l"(d):"l"(a),"l"(b),"l"(c)); return d;
}
__device__ __forceinline__ u64 mul2(u64 a, u64 b){
    u64 d; asm("mul.rn.f32x2 %0,%1,%2;":"=l"(d):"l"(a),"l"(b)); return d;
}

// separable Gaussian weights for size=7, sigma=1.5 (softmax(g_i+g_j+g_k) factors exactly)
#define W0 0.0366328f
#define W1 0.1112808f
#define W2 0.2167453f
#define W3 0.2706821f
__device__ __forceinline__ float wsc(int k){
    return (k==0||k==6) ? W0 : (k==1||k==5) ? W1 : (k==2||k==4) ? W2 : W3;
}

__device__ double g_ssim_acc;

__global__ void ssim_zero_kernel(){ g_ssim_acc = 0.0; }

__global__ __launch_bounds__(NT, 2)
void ssim_main_kernel(const float* __restrict__ X, const float* __restrict__ Y){
    __shared__ u64   sab[INY][INX];    // packed (x, y) raw slice
    __shared__ u64   t01[INY][TX];     // packed (conv_x(x), conv_x(y))
    __shared__ u64   t23[INY][TX];     // packed (conv_x(x^2), conv_x(y^2))
    __shared__ float t4 [INY][TX];     // conv_x(x*y)
    __shared__ float red[NT/32];

    const int t   = threadIdx.x;
    const int txi = t & 15;
    const int q   = t >> 4;

    const int gx0   = blockIdx.x * TX;
    const int gy0   = blockIdx.y * TY;
    const int batch = blockIdx.z >> 2;
    const int chunk = blockIdx.z & 3;
    const int z0    = chunk * ZCS;
    const int z1    = min(z0 + ZCS, OUTD);
    const int nsl   = (z1 + 6) - z0;          // slices to process

    const int plane = D * D;
    const float* xb = X + (size_t)batch * plane * D + (size_t)z0 * plane;
    const float* yb = Y + (size_t)batch * plane * D + (size_t)z0 * plane;

    u64 wp[4];
    wp[0]=pack2(W0,W0); wp[1]=pack2(W1,W1); wp[2]=pack2(W2,W2); wp[3]=pack2(W3,W3);

    // ---- hoisted load-stage indices (4 strided passes over 38x22=836 points) ----
    int  loff[4], lsm[4];
    bool lld[4], lst[4];
    #pragma unroll
    for (int i = 0; i < 4; i++){
        int p  = t + i * NT;
        int ly = p / INX;
        int lx = p - ly * INX;
        lst[i] = (p < INY * INX);
        lld[i] = lst[i] && (gy0 + ly < D) && (gx0 + lx < D);
        loff[i] = (gy0 + ly) * D + (gx0 + lx);
        lsm[i]  = p;
    }

    // per-thread z rings for 2 adjacent y-output rows
    u64   A01[7], A23[7], B01[7], B23[7];
    float A4[7],  B4[7];

    const int  r0 = 2 * q, r1 = 2 * q + 1;
    const bool okx = (gx0 + txi) < OUTD;
    const bool v0  = okx && (gy0 + r0 < OUTD);
    const bool v1  = okx && (gy0 + r1 < OUTD);

    const float c1 = 1e-4f, c2 = 9e-4f;
    float acc = 0.f;

    for (int base = 0; base < nsl; base += 7){
        #pragma unroll
        for (int ph = 0; ph < 7; ph++){
            const int sl = base + ph;
            if (sl >= nsl) break;
            const float* xs = xb + (size_t)sl * plane;
            const float* ys = yb + (size_t)sl * plane;

            // ---- load raw slice (packed) ----
            #pragma unroll
            for (int i = 0; i < 4; i++){
                if (lst[i]){
                    float a = lld[i] ? __ldg(xs + loff[i]) : 0.f;
                    float b = lld[i] ? __ldg(ys + loff[i]) : 0.f;
                    ((u64*)sab)[lsm[i]] = pack2(a, b);
                }
            }
            __syncthreads();

            // ---- x-direction conv (38x16 points, 3 strided passes) ----
            #pragma unroll
            for (int i = 0; i < 3; i++){
                const int row = i * 16 + q;
                if (i < 2 || t < 96){
                    u64 ab = sab[row][txi];
                    float a, b; unpack2(ab, a, b);
                    u64 p01 = mul2(wp[0], ab);
                    u64 p23 = mul2(wp[0], mul2(ab, ab));
                    float s4 = W0 * (a * b);
                    #pragma unroll
                    for (int k = 1; k < 7; k++){
                        ab = sab[row][txi + k];
                        unpack2(ab, a, b);
                        u64 wk2 = wp[k < 4 ? k : 6 - k];
                        p01 = fma2(wk2, ab, p01);
                        p23 = fma2(wk2, mul2(ab, ab), p23);
                        s4  = fmaf(wsc(k), a * b, s4);
                    }
                    t01[row][txi] = p01;
                    t23[row][txi] = p23;
                    t4 [row][txi] = s4;
                }
            }
            __syncthreads();

            // ---- y-direction conv: 2 adjacent outputs, streamed (8 row-taps) ----
            u64 o0_01, o0_23, o1_01 = 0, o1_23 = 0;
            float o0_4, o1_4 = 0.f;
            {
                u64 f01 = t01[r0][txi];
                u64 f23 = t23[r0][txi];
                float f4 = t4[r0][txi];
                o0_01 = mul2(wp[0], f01);
                o0_23 = mul2(wp[0], f23);
                o0_4  = W0 * f4;
                #pragma unroll
                for (int j = 1; j < 8; j++){
                    f01 = t01[r0 + j][txi];
                    f23 = t23[r0 + j][txi];
                    f4  = t4 [r0 + j][txi];
                    if (j < 7){
                        u64 wj = wp[j < 4 ? j : 6 - j];
                        o0_01 = fma2(wj, f01, o0_01);
                        o0_23 = fma2(wj, f23, o0_23);
                        o0_4  = fmaf(wsc(j), f4, o0_4);
                    }
                    const int jm = j - 1;
                    u64 wm = wp[jm < 4 ? jm : 6 - jm];
                    if (j == 1){
                        o1_01 = mul2(wm, f01);
                        o1_23 = mul2(wm, f23);
                        o1_4  = W0 * f4;
                    } else {
                        o1_01 = fma2(wm, f01, o1_01);
                        o1_23 = fma2(wm, f23, o1_23);
                        o1_4  = fmaf(wsc(jm), f4, o1_4);
                    }
                }
            }
            A01[ph] = o0_01; A23[ph] = o0_23; A4[ph] = o0_4;
            B01[ph] = o1_01; B23[ph] = o1_23; B4[ph] = o1_4;

            // ---- z-direction conv + SSIM (ring full after 7 slices) ----
            if (sl >= 6){
                if (v0){
                    const int s0i = (ph + 1) % 7;
                    u64 m01 = mul2(wp[0], A01[s0i]);
                    u64 m23 = mul2(wp[0], A23[s0i]);
                    float m4 = W0 * A4[s0i];
                    #pragma unroll
                    for (int k = 1; k < 7; k++){
                        const int si = (ph + 1 + k) % 7;
                        u64 wk2 = wp[k < 4 ? k : 6 - k];
                        m01 = fma2(wk2, A01[si], m01);
                        m23 = fma2(wk2, A23[si], m23);
                        m4  = fmaf(wsc(k), A4[si], m4);
                    }
                    float mu1, mu2, ex2, ey2;
                    unpack2(m01, mu1, mu2);
                    unpack2(m23, ex2, ey2);
                    float m1s = mu1 * mu1, m2s = mu2 * mu2, mm = mu1 * mu2;
                    float num = (2.f * mm + c1) * (2.f * (m4 - mm) + c2);
                    float den = (m1s + m2s + c1) * ((ex2 - m1s) + (ey2 - m2s) + c2);
                    acc += __fdividef(num, den);
                }
                if (v1){
                    const int s0i = (ph + 1) % 7;
                    u64 m01 = mul2(wp[0], B01[s0i]);
                    u64 m23 = mul2(wp[0], B23[s0i]);
                    float m4 = W0 * B4[s0i];
                    #pragma unroll
                    for (int k = 1; k < 7; k++){
                        const int si = (ph + 1 + k) % 7;
                        u64 wk2 = wp[k < 4 ? k : 6 - k];
                        m01 = fma2(wk2, B01[si], m01);
                        m23 = fma2(wk2, B23[si], m23);
                        m4  = fmaf(wsc(k), B4[si], m4);
                    }
                    float mu1, mu2, ex2, ey2;
                    unpack2(m01, mu1, mu2);
                    unpack2(m23, ex2, ey2);
                    float m1s = mu1 * mu1, m2s = mu2 * mu2, mm = mu1 * mu2;
                    float num = (2.f * mm + c1) * (2.f * (m4 - mm) + c2);
                    float den = (m1s + m2s + c1) * ((ex2 - m1s) + (ey2 - m2s) + c2);
                    acc += __fdividef(num, den);
                }
            }
        }
    }

    // ---- reduction: warp shuffle + cross-warp ----
    #pragma unroll
    for (int o = 16; o > 0; o >>= 1)
        acc += __shfl_xor_sync(0xffffffffu, acc, o);
    if ((t & 31) == 0) red[t >> 5] = acc;
    __syncthreads();
    if (t < 32){
        float v = (t < NT/32) ? red[t] : 0.f;
        #pragma unroll
        for (int o = 16; o > 0; o >>= 1)
            v += __shfl_xor_sync(0xffffffffu, v, o);
        if (t == 0) atomicAdd(&g_ssim_acc, (double)v);
    }
}

__global__ void ssim_finalize_kernel(float* __restrict__ out){
    // N = 2 * 186^3 = 12,869,712
    out[0] = (float)(g_ssim_acc / 12869712.0);
}

extern "C" void kernel_launch(void* const* d_in, const int* in_sizes, int n_in,
                              void* d_out, int out_size){
    const float* x = (const float*)d_in[0];
    const float* y = (const float*)d_in[1];
    float* out = (float*)d_out;

    ssim_zero_kernel<<<1, 1>>>();
    dim3 grid(12, 6, 8);   // 12*16=192 (x), 6*32=192 (y), 2 batches * 4 z-chunks
    ssim_main_kernel<<<grid, NT>>>(x, y);
    ssim_finalize_kernel<<<1, 1>>>(out);
}

// round 3
// speedup vs baseline: 1.6634x; 1.3941x over previous
#include <cuda_runtime.h>

#define D      192
#define PLANE  (192*192)
#define OUTD   186
#define TX     16
#define TY     32
#define INY    38           // TY + 6
#define SAW    24           // padded raw-row width (22 -> 24 floats, 6x16B chunks)
#define T01W   18           // padded t01/t23 row width (u64)
#define T4W    20           // padded t4 row width (f32)
#define ZCS    93           // z chunk: 2 chunks of exactly 93 outputs
#define NSL    99           // slices per chunk = 93 + 6 (static!)
#define NT     256

typedef unsigned long long u64;

__device__ __forceinline__ u64 pack2(float lo, float hi){
    u64 r; asm("mov.b64 %0,{%1,%2};":"=l"(r):"f"(lo),"f"(hi)); return r;
}
__device__ __forceinline__ void unpack2(u64 v, float& lo, float& hi){
    asm("mov.b64 {%0,%1},%2;":"=f"(lo),"=f"(hi):"l"(v));
}
__device__ __forceinline__ u64 fma2(u64 a, u64 b, u64 c){
    u64 d; asm("fma.rn.f32x2 %0,%1,%2,%3;":"=l"(d):"l"(a),"l"(b),"l"(c)); return d;
}
__device__ __forceinline__ u64 mul2(u64 a, u64 b){
    u64 d; asm("mul.rn.f32x2 %0,%1,%2;":"=l"(d):"l"(a),"l"(b)); return d;
}

// separable Gaussian weights, size 7, sigma 1.5
#define W0 0.0366328f
#define W1 0.1112808f
#define W2 0.2167453f
#define W3 0.2706821f
__device__ __forceinline__ float wsc(int k){
    return (k==0||k==6) ? W0 : (k==1||k==5) ? W1 : (k==2||k==4) ? W2 : W3;
}

#define CP_ASYNC16(dst, src) \
    asm volatile("cp.async.cg.shared.global [%0], [%1], 16;" :: "r"(dst), "l"(src))
#define CP_COMMIT()  asm volatile("cp.async.commit_group;")
#define CP_WAIT0()   asm volatile("cp.async.wait_group 0;")

__device__ double g_ssim_acc;

__global__ void ssim_zero_kernel(){ g_ssim_acc = 0.0; }

__global__ __launch_bounds__(NT, 2)
void ssim_main_kernel(const float* __restrict__ X, const float* __restrict__ Y){
    __shared__ float sa [2][INY][SAW];
    __shared__ float sb [2][INY][SAW];
    __shared__ u64   t01[2][INY][T01W];
    __shared__ u64   t23[2][INY][T01W];
    __shared__ float t4 [2][INY][T4W];
    __shared__ float red[NT/32];

    const int t   = threadIdx.x;
    const int txi = t & 15;
    const int q   = t >> 4;

    const int gx0   = blockIdx.x * TX;
    const int gy0   = blockIdx.y * TY;
    const int batch = blockIdx.z >> 1;
    const int chunk = blockIdx.z & 1;
    const int z0    = chunk * ZCS;

    const float* xb = X + (size_t)batch * PLANE * D + (size_t)z0 * PLANE;
    const float* yb = Y + (size_t)batch * PLANE * D + (size_t)z0 * PLANE;

    u64 wp[4];
    wp[0]=pack2(W0,W0); wp[1]=pack2(W1,W1); wp[2]=pack2(W2,W2); wp[3]=pack2(W3,W3);

    // ---- per-thread cp.async chunk assignments (2 chunks; 456 total) ----
    // cid < 228 -> array a (X); else array b (Y). Within: r = c/6, ck = c%6.
    const float* p1;  const float* p2;
    unsigned s1, s2;  bool have2 = (t < 200);
    {
        int cid1 = t;
        int c1   = (cid1 < 228) ? cid1 : cid1 - 228;
        int r1_  = c1 / 6, ck1 = c1 - 6 * r1_;
        int gy1  = min(gy0 + r1_, D - 1);
        int gxc1 = gx0 + ck1 * 4; if (gxc1 + 3 >= D) gxc1 = gx0;
        p1 = ((cid1 < 228) ? xb : yb) + gy1 * D + gxc1;
        s1 = (unsigned)__cvta_generic_to_shared(
                 ((cid1 < 228) ? &sa[0][r1_][ck1*4] : &sb[0][r1_][ck1*4]));

        int cid2 = t + 256;
        int c2   = cid2 - 228;              // cid2 >= 256 > 228 always -> array b
        int r2_  = c2 / 6, ck2 = c2 - 6 * r2_;
        int gy2  = min(gy0 + r2_, D - 1);
        int gxc2 = gx0 + ck2 * 4; if (gxc2 + 3 >= D) gxc2 = gx0;
        p2 = yb + gy2 * D + gxc2;
        s2 = (unsigned)__cvta_generic_to_shared(&sb[0][r2_][ck2*4]);
    }
    const unsigned BUFOFF = (unsigned)(INY * SAW * sizeof(float));  // 3648

    // x-conv thread mapping: 152 active threads, 4 output cols each
    const bool xact = (t < 152);
    const int  xrow = t >> 2;
    const int  xc0  = (t & 3) * 4;

    // per-thread z rings: 2 output rows x (01,23 packed + xy scalar) x 7
    u64   A01[7], A23[7], B01[7], B23[7];
    float A4[7],  B4[7];

    const int  r0 = 2 * q, r1 = 2 * q + 1;
    const bool okx = (gx0 + txi) < OUTD;
    const bool v0  = okx && (gy0 + r0 < OUTD);
    const bool v1  = okx && (gy0 + r1 < OUTD);

    const float c1 = 1e-4f, c2 = 9e-4f;
    float acc = 0.f;

    // ---- prologue: async-load slice 0 into buffer 0 ----
    CP_ASYNC16(s1, p1);
    if (have2) CP_ASYNC16(s2, p2);
    CP_COMMIT();
    p1 += PLANE; p2 += PLANE;

    // ---- pipelined slice loop: it in [0, NSL]; x-conv slice it, y/z slice it-1 ----
    for (int base = 0; base <= NSL; base += 7){
        #pragma unroll
        for (int ph = 0; ph < 7; ++ph){
            const int it = base + ph;
            if (it > NSL) break;
            const int bit = it & 1;

            CP_WAIT0();
            __syncthreads();

            // issue load of slice it+1 (last x-conv slice is NSL-1 = 98)
            if (it < NSL - 1){
                unsigned o = ((it + 1) & 1) * BUFOFF;
                CP_ASYNC16(s1 + o, p1);
                if (have2) CP_ASYNC16(s2 + o, p2);
                CP_COMMIT();
                p1 += PLANE; p2 += PLANE;
            } else {
                CP_COMMIT();   // keep wait_group 0 harmless
            }

            // ---- x-direction conv of slice it ----
            if (it < NSL && xact){
                const float* pa = &sa[bit][xrow][xc0];
                const float* pb = &sb[bit][xrow][xc0];
                float av[12], bv[12];
                {
                    float4 u = *(const float4*)(pa);
                    float4 v = *(const float4*)(pa + 4);
                    float2 w2 = *(const float2*)(pa + 8);
                    av[0]=u.x; av[1]=u.y; av[2]=u.z; av[3]=u.w;
                    av[4]=v.x; av[5]=v.y; av[6]=v.z; av[7]=v.w;
                    av[8]=w2.x; av[9]=w2.y; av[10]=0.f; av[11]=0.f;
                    u = *(const float4*)(pb);
                    v = *(const float4*)(pb + 4);
                    w2 = *(const float2*)(pb + 8);
                    bv[0]=u.x; bv[1]=u.y; bv[2]=u.z; bv[3]=u.w;
                    bv[4]=v.x; bv[5]=v.y; bv[6]=v.z; bv[7]=v.w;
                    bv[8]=w2.x; bv[9]=w2.y; bv[10]=0.f; bv[11]=0.f;
                }
                u64 a01[4], a23[4]; float a4[4];
                #pragma unroll
                for (int m = 0; m < 10; ++m){
                    u64 pab = pack2(av[m], bv[m]);
                    u64 sq  = mul2(pab, pab);
                    float xy = av[m] * bv[m];
                    #pragma unroll
                    for (int c = 0; c < 4; ++c){
                        int k = m - c;
                        if (k >= 0 && k <= 6){
                            u64 wk2 = wp[k < 4 ? k : 6 - k];
                            float wk = wsc(k);
                            if (k == 0){
                                a01[c] = mul2(wk2, pab);
                                a23[c] = mul2(wk2, sq);
                                a4[c]  = wk * xy;
                            } else {
                                a01[c] = fma2(wk2, pab, a01[c]);
                                a23[c] = fma2(wk2, sq,  a23[c]);
                                a4[c]  = fmaf(wk, xy, a4[c]);
                            }
                        }
                    }
                }
                ulonglong2 v01a; v01a.x = a01[0]; v01a.y = a01[1];
                ulonglong2 v01b; v01b.x = a01[2]; v01b.y = a01[3];
                *(ulonglong2*)&t01[bit][xrow][xc0]     = v01a;
                *(ulonglong2*)&t01[bit][xrow][xc0 + 2] = v01b;
                ulonglong2 v23a; v23a.x = a23[0]; v23a.y = a23[1];
                ulonglong2 v23b; v23b.x = a23[2]; v23b.y = a23[3];
                *(ulonglong2*)&t23[bit][xrow][xc0]     = v23a;
                *(ulonglong2*)&t23[bit][xrow][xc0 + 2] = v23b;
                float4 v4; v4.x = a4[0]; v4.y = a4[1]; v4.z = a4[2]; v4.w = a4[3];
                *(float4*)&t4[bit][xrow][xc0] = v4;
            }

            // ---- y-direction conv + ring + z-conv + SSIM for slice sy = it-1 ----
            if (it >= 1){
                const int bp = bit ^ 1;
                u64 o0_01, o0_23, o1_01, o1_23;
                float o0_4, o1_4;
                {
                    u64 f01 = t01[bp][r0][txi];
                    u64 f23 = t23[bp][r0][txi];
                    float f4 = t4[bp][r0][txi];
                    o0_01 = mul2(wp[0], f01);
                    o0_23 = mul2(wp[0], f23);
                    o0_4  = W0 * f4;
                    o1_01 = 0; o1_23 = 0; o1_4 = 0.f;
                    #pragma unroll
                    for (int j = 1; j < 8; ++j){
                        f01 = t01[bp][r0 + j][txi];
                        f23 = t23[bp][r0 + j][txi];
                        f4  = t4 [bp][r0 + j][txi];
                        if (j < 7){
                            u64 wj = wp[j < 4 ? j : 6 - j];
                            o0_01 = fma2(wj, f01, o0_01);
                            o0_23 = fma2(wj, f23, o0_23);
                            o0_4  = fmaf(wsc(j), f4, o0_4);
                        }
                        const int jm = j - 1;
                        u64 wm = wp[jm < 4 ? jm : 6 - jm];
                        if (j == 1){
                            o1_01 = mul2(wm, f01);
                            o1_23 = mul2(wm, f23);
                            o1_4  = W0 * f4;
                        } else {
                            o1_01 = fma2(wm, f01, o1_01);
                            o1_23 = fma2(wm, f23, o1_23);
                            o1_4  = fmaf(wsc(jm), f4, o1_4);
                        }
                    }
                }
                const int RIDX = (ph + 6) % 7;       // (it-1) % 7, compile-time
                A01[RIDX] = o0_01; A23[RIDX] = o0_23; A4[RIDX] = o0_4;
                B01[RIDX] = o1_01; B23[RIDX] = o1_23; B4[RIDX] = o1_4;

                if (it >= 7){                         // sy >= 6: ring full
                    if (v0){
                        u64 m01 = mul2(wp[0], A01[ph % 7]);
                        u64 m23 = mul2(wp[0], A23[ph % 7]);
                        float m4 = W0 * A4[ph % 7];
                        #pragma unroll
                        for (int k = 1; k < 7; ++k){
                            const int si = (ph + k) % 7;
                            u64 wk2 = wp[k < 4 ? k : 6 - k];
                            m01 = fma2(wk2, A01[si], m01);
                            m23 = fma2(wk2, A23[si], m23);
                            m4  = fmaf(wsc(k), A4[si], m4);
                        }
                        float mu1, mu2, ex2, ey2;
                        unpack2(m01, mu1, mu2);
                        unpack2(m23, ex2, ey2);
                        float m1s = mu1*mu1, m2s = mu2*mu2, mm = mu1*mu2;
                        float num = (2.f*mm + c1) * (2.f*(m4 - mm) + c2);
                        float den = (m1s + m2s + c1) * ((ex2 - m1s) + (ey2 - m2s) + c2);
                        acc += __fdividef(num, den);
                    }
                    if (v1){
                        u64 m01 = mul2(wp[0], B01[ph % 7]);
                        u64 m23 = mul2(wp[0], B23[ph % 7]);
                        float m4 = W0 * B4[ph % 7];
                        #pragma unroll
                        for (int k = 1; k < 7; ++k){
                            const int si = (ph + k) % 7;
                            u64 wk2 = wp[k < 4 ? k : 6 - k];
                            m01 = fma2(wk2, B01[si], m01);
                            m23 = fma2(wk2, B23[si], m23);
                            m4  = fmaf(wsc(k), B4[si], m4);
                        }
                        float mu1, mu2, ex2, ey2;
                        unpack2(m01, mu1, mu2);
                        unpack2(m23, ex2, ey2);
                        float m1s = mu1*mu1, m2s = mu2*mu2, mm = mu1*mu2;
                        float num = (2.f*mm + c1) * (2.f*(m4 - mm) + c2);
                        float den = (m1s + m2s + c1) * ((ex2 - m1s) + (ey2 - m2s) + c2);
                        acc += __fdividef(num, den);
                    }
                }
            }
        }
    }

    // ---- reduction ----
    #pragma unroll
    for (int o = 16; o > 0; o >>= 1)
        acc += __shfl_xor_sync(0xffffffffu, acc, o);
    if ((t & 31) == 0) red[t >> 5] = acc;
    __syncthreads();
    if (t < 32){
        float v = (t < NT/32) ? red[t] : 0.f;
        #pragma unroll
        for (int o = 16; o > 0; o >>= 1)
            v += __shfl_xor_sync(0xffffffffu, v, o);
        if (t == 0) atomicAdd(&g_ssim_acc, (double)v);
    }
}

__global__ void ssim_finalize_kernel(float* __restrict__ out){
    out[0] = (float)(g_ssim_acc / 12869712.0);   // 2 * 186^3
}

extern "C" void kernel_launch(void* const* d_in, const int* in_sizes, int n_in,
                              void* d_out, int out_size){
    const float* x = (const float*)d_in[0];
    const float* y = (const float*)d_in[1];
    float* out = (float*)d_out;

    ssim_zero_kernel<<<1, 1>>>();
    dim3 grid(12, 6, 4);   // x tiles, y tiles, 2 batches * 2 z-chunks = 288 blocks (1 wave)
    ssim_main_kernel<<<grid, NT>>>(x, y);
    ssim_finalize_kernel<<<1, 1>>>(out);
}